// round 5
// baseline (speedup 1.0000x reference)
#include <cuda_runtime.h>
#include <cuda_bf16.h>
#include <cstdint>

// Problem constants
#define Bsz   128
#define Gsz   100
#define Lz    16
#define HL    512
#define Dd    64
#define OUTSZ 8450   // 64+1 + 4096+64 + 4096+64 + 64+1

typedef unsigned long long ULL;

// Scratch (device globals: no allocation allowed). All transposed [k][m].
__device__ __align__(16) float g_h0t[HL * Bsz];
__device__ __align__(16) float g_h1t[HL * Bsz];
__device__ __align__(16) float g_h2t[HL * Bsz];
__device__ __align__(16) float g_wab[Bsz * OUTSZ];

__device__ __forceinline__ float leaky(float v) { return v > 0.f ? v : 0.01f * v; }

// ---- packed fp32x2 helpers (sm_100 packed dual-FMA; bit-exact IEEE fp32) ----
__device__ __forceinline__ ULL pack2(float lo, float hi) {
    ULL r; asm("mov.b64 %0, {%1, %2};" : "=l"(r) : "f"(lo), "f"(hi)); return r;
}
__device__ __forceinline__ ULL dup2(float x) {
    ULL r; asm("mov.b64 %0, {%1, %1};" : "=l"(r) : "f"(x)); return r;
}
__device__ __forceinline__ void unpack2(ULL v, float& lo, float& hi) {
    asm("mov.b64 {%0, %1}, %2;" : "=f"(lo), "=f"(hi) : "l"(v));
}
__device__ __forceinline__ void ffma2(ULL& acc, ULL a, ULL b) {
    asm("fma.rn.f32x2 %0, %1, %2, %0;" : "+l"(acc) : "l"(a), "l"(b));
}

// ---------------------------------------------------------------------------
// Kernel 1: h0t[j][b] = leaky(z[b] . hW0[:,j] + hb0[j])   (transposed store)
// ---------------------------------------------------------------------------
__global__ void k_h0(const float* __restrict__ z, const float* __restrict__ hW0,
                     const float* __restrict__ hb0) {
    __shared__ float zs[Lz];
    int b = blockIdx.x;
    int j = threadIdx.x;
    if (j < Lz) zs[j] = z[b * Lz + j];
    __syncthreads();
    float acc = hb0[j];
#pragma unroll
    for (int i = 0; i < Lz; i++) acc = fmaf(zs[i], hW0[i * HL + j], acc);
    g_h0t[j * Bsz + b] = leaky(acc);
}

// ---------------------------------------------------------------------------
// Hidden GEMM (pipelined, trans-A, trans-out):
//   Ct[n][m] = leaky( sum_k At[k][m] * W[k][n] + bias[n] )
// BM=128, BN=8, BK=64, S=3 stages, 256 threads, grid=64.
// ---------------------------------------------------------------------------
__global__ void __launch_bounds__(256, 1) hid_gemm(const float* __restrict__ At,
                                                   const float* __restrict__ W,
                                                   const float* __restrict__ bias,
                                                   float* __restrict__ Ct) {
    constexpr int BK = 64, BN = 8, S = 3, K = 512, NT = K / BK;
    constexpr int ASZ = BK * 128;
    constexpr int BSZ = BK * BN;
    extern __shared__ float sm[];
    float* As = sm;
    float* Bs = sm + S * ASZ;

    const int tid  = threadIdx.x;
    const int n0   = blockIdx.x * BN;
    const int tcol = tid & 7;
    const int trow = tid >> 3;
    const int m0   = trow * 4;

    auto load_tile = [&](int t, int s) {
        float* Ad = As + s * ASZ;
        const float* Ag = At + t * BK * 128;
#pragma unroll
        for (int u = 0; u < 8; u++) {
            int idx = tid + u * 256;
            int row = idx >> 5, col = (idx & 31) << 2;
            uint32_t d = (uint32_t)__cvta_generic_to_shared(Ad + row * 128 + col);
            asm volatile("cp.async.cg.shared.global [%0], [%1], 16;"
                         :: "r"(d), "l"(Ag + row * 128 + col));
        }
        if (tid < 128) {
            int row = tid >> 1, c = (tid & 1) << 2;
            float* Bd = Bs + s * BSZ;
            uint32_t d = (uint32_t)__cvta_generic_to_shared(Bd + row * BN + c);
            asm volatile("cp.async.ca.shared.global [%0], [%1], 16;"
                         :: "r"(d), "l"(W + (size_t)(t * BK + row) * HL + n0 + c));
        }
        asm volatile("cp.async.commit_group;");
    };

    ULL acc0 = 0, acc1 = 0;
    load_tile(0, 0);
    load_tile(1, 1);

    for (int t = 0; t < NT; t++) {
        if (t + 1 < NT) asm volatile("cp.async.wait_group 1;");
        else            asm volatile("cp.async.wait_group 0;");
        __syncthreads();
        if (t + 2 < NT) load_tile(t + 2, (t + 2) % S);

        const float* As_ = As + (t % S) * ASZ;
        const float* Bs_ = Bs + (t % S) * BSZ;
#pragma unroll
        for (int kk = 0; kk < BK; kk++) {
            const ULL* ap = reinterpret_cast<const ULL*>(As_ + kk * 128 + m0);
            ULL a0 = ap[0], a1 = ap[1];
            ULL bd = dup2(Bs_[kk * BN + tcol]);
            ffma2(acc0, a0, bd);
            ffma2(acc1, a1, bd);
        }
        __syncthreads();
    }

    float v0, v1, v2, v3;
    unpack2(acc0, v0, v1);
    unpack2(acc1, v2, v3);
    int gn = n0 + tcol;
    float bb = bias[gn];
    float4 out = make_float4(leaky(v0 + bb), leaky(v1 + bb),
                             leaky(v2 + bb), leaky(v3 + bb));
    *reinterpret_cast<float4*>(Ct + gn * Bsz + m0) = out;
}
#define HID_SMEM_BYTES ((3 * (64 * 128) + 3 * (64 * 8)) * 4)

// ---------------------------------------------------------------------------
// wab GEMM: C(128, 8450) = At^T(128,512) @ W(512,8450) + bias
// 512 threads, BN=64, BK=32, S=4. TM=8/TN=2 per thread; trow constant per
// warp -> A loads are pure smem broadcasts. Grid = 133 (one wave).
// ---------------------------------------------------------------------------
__global__ void __launch_bounds__(512, 1) wab_gemm(const float* __restrict__ At,
                                                   const float* __restrict__ W,
                                                   const float* __restrict__ bias,
                                                   float* __restrict__ C) {
    constexpr int BK = 32, BN = 64, S = 4, K = 512, NT = K / BK, N = OUTSZ;
    constexpr int ASZ = BK * 128, BSZ = BK * BN;
    extern __shared__ float sm[];
    float* As = sm;
    float* Bs = sm + S * ASZ;

    const int tid  = threadIdx.x;
    const int n0   = blockIdx.x * BN;
    const int tcol = tid & 31;          // lane: n-offset tcol*2
    const int trow = tid >> 5;          // warp id: m-offset trow*8 (uniform/warp)

    auto load_tile = [&](int t, int s) {
        float* Ad = As + s * ASZ;
        const float* Ag = At + t * BK * 128;
#pragma unroll
        for (int u = 0; u < 2; u++) {
            int idx = tid + u * 512;               // 1024 16B chunks
            int row = idx >> 5, col = (idx & 31) << 2;
            uint32_t d = (uint32_t)__cvta_generic_to_shared(Ad + row * 128 + col);
            asm volatile("cp.async.cg.shared.global [%0], [%1], 16;"
                         :: "r"(d), "l"(Ag + row * 128 + col));
        }
        float* Bd = Bs + s * BSZ;                  // 1024 8B chunks
#pragma unroll
        for (int u = 0; u < 2; u++) {
            int idx = tid + u * 512;
            int row = idx >> 5, c = (idx & 31) << 1;
            int gn = n0 + c;
            uint32_t d = (uint32_t)__cvta_generic_to_shared(Bd + row * BN + c);
            const float* src = W + (size_t)(t * BK + row) * N + (gn < N ? gn : 0);
            int bytes = (gn < N) ? 8 : 0;
            asm volatile("cp.async.ca.shared.global [%0], [%1], 8, %2;"
                         :: "r"(d), "l"(src), "r"(bytes));
        }
        asm volatile("cp.async.commit_group;");
    };

    ULL acc[4][2];
#pragma unroll
    for (int i = 0; i < 4; i++) { acc[i][0] = 0ull; acc[i][1] = 0ull; }

    load_tile(0, 0);
    load_tile(1, 1);
    load_tile(2, 2);

    for (int t = 0; t < NT; t++) {
        int rem = NT - 1 - t;
        if (rem >= 2)      asm volatile("cp.async.wait_group 2;");
        else if (rem == 1) asm volatile("cp.async.wait_group 1;");
        else               asm volatile("cp.async.wait_group 0;");
        __syncthreads();
        if (t + S - 1 < NT) load_tile(t + S - 1, (t + S - 1) % S);

        const float* As_ = As + (t % S) * ASZ;
        const float* Bs_ = Bs + (t % S) * BSZ;
#pragma unroll
        for (int kk = 0; kk < BK; kk++) {
            // A: same address for every lane in the warp -> broadcast LDS.128
            const ULL* ap = reinterpret_cast<const ULL*>(As_ + kk * 128 + trow * 8);
            ULL a0 = ap[0], a1 = ap[1], a2 = ap[2], a3 = ap[3];
            float2 bv = *reinterpret_cast<const float2*>(Bs_ + kk * BN + tcol * 2);
            ULL b0 = dup2(bv.x), b1 = dup2(bv.y);
            ffma2(acc[0][0], a0, b0); ffma2(acc[0][1], a0, b1);
            ffma2(acc[1][0], a1, b0); ffma2(acc[1][1], a1, b1);
            ffma2(acc[2][0], a2, b0); ffma2(acc[2][1], a2, b1);
            ffma2(acc[3][0], a3, b0); ffma2(acc[3][1], a3, b1);
        }
        __syncthreads();
    }

#pragma unroll
    for (int j = 0; j < 2; j++) {
        int gn = n0 + tcol * 2 + j;
        if (gn < N) {
            float bb = bias[gn];
#pragma unroll
            for (int i = 0; i < 4; i++) {
                float lo, hi;
                unpack2(acc[i][j], lo, hi);
                int m = trow * 8 + 2 * i;
                C[(size_t)m * N + gn]       = lo + bb;
                C[(size_t)(m + 1) * N + gn] = hi + bb;
            }
        }
    }
}
#define WAB_SMEM_BYTES ((4 * 32 * 128 + 4 * 32 * 64) * 4)   // 96 KB

// ---------------------------------------------------------------------------
// Decoder: one block per b, 256 threads. Thread (g, half) computes 32 of the
// 64 outputs of each hidden layer; activations ping-pong between two smem
// buffers. Weight LDS are warp-broadcast; activation LDS conflict-free.
// ---------------------------------------------------------------------------
#define SW1 0        // 4096
#define SW2 4096     // 4096
#define SW0 8192     // 64
#define SW3 8256     // 64
#define SB1 8320     // 64
#define SB2 8384     // 64
#define SB0 8448
#define SB3 8449
#define XA  8452     // 100 rows x 65
#define XB  (XA + 100 * 65)
#define XSTR 65
#define DEC_SMEM_FLOATS (XB + 100 * 65)
#define DEC_SMEM_BYTES  (DEC_SMEM_FLOATS * 4)

__device__ __forceinline__ void dec_layer_half(const float* __restrict__ s,
                                               int src, int dst, int gl, int c0,
                                               int wbase, int bbase,
                                               float* __restrict__ sw) {
    ULL acc[16];
#pragma unroll
    for (int q = 0; q < 8; q++) {
        float4 bb = *reinterpret_cast<const float4*>(s + bbase + c0 + q * 4);
        acc[2 * q]     = pack2(bb.x, bb.y);
        acc[2 * q + 1] = pack2(bb.z, bb.w);
    }
#pragma unroll 4
    for (int i = 0; i < Dd; i++) {
        ULL vd = dup2(s[src + gl * XSTR + i]);
        const ULL* wr = reinterpret_cast<const ULL*>(s + wbase + i * Dd + c0);
#pragma unroll
        for (int q = 0; q < 16; q++) ffma2(acc[q], vd, wr[q]);
    }
#pragma unroll
    for (int q = 0; q < 16; q++) {
        float lo, hi;
        unpack2(acc[q], lo, hi);
        sw[dst + gl * XSTR + c0 + 2 * q]     = __sinf(lo);
        sw[dst + gl * XSTR + c0 + 2 * q + 1] = __sinf(hi);
    }
}

__global__ void __launch_bounds__(256) decoder_kernel(const float* __restrict__ log_P,
                                                      float* __restrict__ out) {
    extern __shared__ float s[];
    const int b = blockIdx.x;
    const int tid = threadIdx.x;
    const int half = tid >> 7;         // 0 or 1
    const int gl   = tid & 127;        // g index
    const int c0   = half * 32;        // output-column offset
    const bool act = gl < Gsz;
    const float* gw = g_wab + (size_t)b * OUTSZ;

    for (int i = tid; i < 4096; i += 256) s[SW1 + i] = gw[65 + i];
    for (int i = tid; i < 4096; i += 256) s[SW2 + i] = gw[4225 + i];
    if (tid < 64) {
        s[SW0 + tid] = gw[tid];
        s[SW3 + tid] = gw[8385 + tid];
        s[SB1 + tid] = gw[4161 + tid];
        s[SB2 + tid] = gw[8321 + tid];
    }
    if (tid == 0) { s[SB0] = gw[64]; s[SB3] = gw[8449]; }
    __syncthreads();

    if (act) {
        float x = log_P[b * Gsz + gl] * (1.f / 3.f);
        float b0 = s[SB0];
#pragma unroll
        for (int j = 0; j < 32; j++) {
            int jj = c0 + j;
            s[XA + gl * XSTR + jj] = __sinf(30.f * fmaf(x, s[SW0 + jj], b0));
        }
    }
    __syncthreads();
    if (act) dec_layer_half(s, XA, XB, gl, c0, SW1, SB1, s);
    __syncthreads();
    if (act) dec_layer_half(s, XB, XA, gl, c0, SW2, SB2, s);
    __syncthreads();

    if (act && half == 0) {
        float accf = s[SB3];
#pragma unroll
        for (int i = 0; i < Dd; i++)
            accf = fmaf(s[XA + gl * XSTR + i], s[SW3 + i], accf);
        out[b * Gsz + gl] = fmaf(accf, 500.f, 1500.f);
    }
}

// ---------------------------------------------------------------------------
// Launch
// ---------------------------------------------------------------------------
extern "C" void kernel_launch(void* const* d_in, const int* in_sizes, int n_in,
                              void* d_out, int out_size) {
    const float* z     = (const float*)d_in[0];
    const float* log_P = (const float*)d_in[1];
    const float* hW0   = (const float*)d_in[2];
    const float* hb0   = (const float*)d_in[3];
    const float* hW1   = (const float*)d_in[4];
    const float* hb1   = (const float*)d_in[5];
    const float* hW2   = (const float*)d_in[6];
    const float* hb2   = (const float*)d_in[7];
    const float* hWo   = (const float*)d_in[8];
    const float* hbo   = (const float*)d_in[9];
    float* out = (float*)d_out;

    float *h0tp, *h1tp, *h2tp, *wabp;
    cudaGetSymbolAddress((void**)&h0tp, g_h0t);
    cudaGetSymbolAddress((void**)&h1tp, g_h1t);
    cudaGetSymbolAddress((void**)&h2tp, g_h2t);
    cudaGetSymbolAddress((void**)&wabp, g_wab);

    cudaFuncSetAttribute(hid_gemm, cudaFuncAttributeMaxDynamicSharedMemorySize,
                         HID_SMEM_BYTES);
    cudaFuncSetAttribute(wab_gemm, cudaFuncAttributeMaxDynamicSharedMemorySize,
                         WAB_SMEM_BYTES);
    cudaFuncSetAttribute(decoder_kernel, cudaFuncAttributeMaxDynamicSharedMemorySize,
                         DEC_SMEM_BYTES);

    k_h0<<<Bsz, HL>>>(z, hW0, hb0);
    hid_gemm<<<HL / 8, 256, HID_SMEM_BYTES>>>(h0tp, hW1, hb1, h1tp);
    hid_gemm<<<HL / 8, 256, HID_SMEM_BYTES>>>(h1tp, hW2, hb2, h2tp);
    wab_gemm<<<(OUTSZ + 63) / 64, 512, WAB_SMEM_BYTES>>>(h2tp, hWo, hbo, wabp);
    decoder_kernel<<<Bsz, 256, DEC_SMEM_BYTES>>>(log_P, out);
}

// round 6
// speedup vs baseline: 1.0798x; 1.0798x over previous
#include <cuda_runtime.h>
#include <cuda_bf16.h>
#include <cstdint>

// Problem constants
#define Bsz   128
#define Gsz   100
#define Lz    16
#define HL    512
#define Dd    64
#define OUTSZ 8450   // 64+1 + 4096+64 + 4096+64 + 64+1

typedef unsigned long long ULL;

// Scratch (device globals: no allocation allowed). All transposed [k][m].
__device__ __align__(16) float g_h0t[HL * Bsz];
__device__ __align__(16) float g_h1t[HL * Bsz];
__device__ __align__(16) float g_h2t[HL * Bsz];
__device__ __align__(16) float g_wab[Bsz * OUTSZ];

__device__ __forceinline__ float leaky(float v) { return v > 0.f ? v : 0.01f * v; }

// ---- packed fp32x2 helpers (sm_100 packed dual-FMA; bit-exact IEEE fp32) ----
__device__ __forceinline__ ULL pack2(float lo, float hi) {
    ULL r; asm("mov.b64 %0, {%1, %2};" : "=l"(r) : "f"(lo), "f"(hi)); return r;
}
__device__ __forceinline__ ULL dup2(float x) {
    ULL r; asm("mov.b64 %0, {%1, %1};" : "=l"(r) : "f"(x)); return r;
}
__device__ __forceinline__ void unpack2(ULL v, float& lo, float& hi) {
    asm("mov.b64 {%0, %1}, %2;" : "=f"(lo), "=f"(hi) : "l"(v));
}
__device__ __forceinline__ void ffma2(ULL& acc, ULL a, ULL b) {
    asm("fma.rn.f32x2 %0, %1, %2, %0;" : "+l"(acc) : "l"(a), "l"(b));
}
__device__ __forceinline__ void fadd2(ULL& acc, ULL b) {
    asm("add.rn.f32x2 %0, %0, %1;" : "+l"(acc) : "l"(b));
}

// ---------------------------------------------------------------------------
// Kernel 1: h0t[j][b] = leaky(z[b] . hW0[:,j] + hb0[j])   (transposed store)
// ---------------------------------------------------------------------------
__global__ void k_h0(const float* __restrict__ z, const float* __restrict__ hW0,
                     const float* __restrict__ hb0) {
    __shared__ float zs[Lz];
    int b = blockIdx.x;
    int j = threadIdx.x;
    if (j < Lz) zs[j] = z[b * Lz + j];
    __syncthreads();
    float acc = hb0[j];
#pragma unroll
    for (int i = 0; i < Lz; i++) acc = fmaf(zs[i], hW0[i * HL + j], acc);
    g_h0t[j * Bsz + b] = leaky(acc);
}

// ---------------------------------------------------------------------------
// Hidden GEMM, split-K over 2 warpgroups (512 threads):
//   Ct[n][m] = leaky( sum_k At[k][m] * W[k][n] + bias[n] )
// BM=128, BN=8, BK=32; each warpgroup handles 8 of 16 k-tiles with its own
// S=3 cp.async pipeline and named barrier. Grid=64.
// ---------------------------------------------------------------------------
__global__ void __launch_bounds__(512, 1) hid_gemm(const float* __restrict__ At,
                                                   const float* __restrict__ W,
                                                   const float* __restrict__ bias,
                                                   float* __restrict__ Ct) {
    constexpr int BK = 32, BN = 8, S = 3, NTH = 8;     // 8 tiles per half
    constexpr int ASZ = BK * 128, BSZ = BK * BN;       // 4096, 256
    constexpr int HSZ = S * (ASZ + BSZ);               // per-half floats
    extern __shared__ float sm[];

    const int tid  = threadIdx.x;
    const int wg   = tid >> 8;          // 0 or 1
    const int wtid = tid & 255;
    float* As = sm + wg * HSZ;
    float* Bs = As + S * ASZ;

    const int n0   = blockIdx.x * BN;
    const int tcol = wtid & 7;
    const int trow = wtid >> 3;
    const int m0   = trow * 4;

    auto load_tile = [&](int t, int s) {
        int gt = wg * NTH + t;                          // global k-tile
        float* Ad = As + s * ASZ;
        const float* Ag = At + gt * BK * 128;
#pragma unroll
        for (int u = 0; u < 4; u++) {
            int idx = wtid + u * 256;                   // 1024 16B chunks
            int row = idx >> 5, col = (idx & 31) << 2;
            uint32_t d = (uint32_t)__cvta_generic_to_shared(Ad + row * 128 + col);
            asm volatile("cp.async.cg.shared.global [%0], [%1], 16;"
                         :: "r"(d), "l"(Ag + row * 128 + col));
        }
        if (wtid < 64) {                                // B: 32 rows x 2 chunks
            int row = wtid >> 1, c = (wtid & 1) << 2;
            float* Bd = Bs + s * BSZ;
            uint32_t d = (uint32_t)__cvta_generic_to_shared(Bd + row * BN + c);
            asm volatile("cp.async.ca.shared.global [%0], [%1], 16;"
                         :: "r"(d), "l"(W + (size_t)(gt * BK + row) * HL + n0 + c));
        }
        asm volatile("cp.async.commit_group;");
    };

    ULL acc0 = 0, acc1 = 0;
    load_tile(0, 0);
    load_tile(1, 1);

    for (int t = 0; t < NTH; t++) {
        if (t + 1 < NTH) asm volatile("cp.async.wait_group 1;");
        else             asm volatile("cp.async.wait_group 0;");
        asm volatile("bar.sync %0, 256;" :: "r"(wg + 1));
        if (t + 2 < NTH) load_tile(t + 2, (t + 2) % S);

        const float* As_ = As + (t % S) * ASZ;
        const float* Bs_ = Bs + (t % S) * BSZ;
#pragma unroll
        for (int kk = 0; kk < BK; kk++) {
            const ULL* ap = reinterpret_cast<const ULL*>(As_ + kk * 128 + m0);
            ULL a0 = ap[0], a1 = ap[1];
            ULL bd = dup2(Bs_[kk * BN + tcol]);
            ffma2(acc0, a0, bd);
            ffma2(acc1, a1, bd);
        }
        asm volatile("bar.sync %0, 256;" :: "r"(wg + 1));
    }

    // Cross-warpgroup reduction (reuse smem after full-block sync)
    __syncthreads();
    ULL* red = reinterpret_cast<ULL*>(sm);
    if (wg == 1) {
        red[wtid * 2]     = acc0;
        red[wtid * 2 + 1] = acc1;
    }
    __syncthreads();
    if (wg == 0) {
        fadd2(acc0, red[wtid * 2]);
        fadd2(acc1, red[wtid * 2 + 1]);
        float v0, v1, v2, v3;
        unpack2(acc0, v0, v1);
        unpack2(acc1, v2, v3);
        int gn = n0 + tcol;
        float bb = bias[gn];
        float4 out = make_float4(leaky(v0 + bb), leaky(v1 + bb),
                                 leaky(v2 + bb), leaky(v3 + bb));
        *reinterpret_cast<float4*>(Ct + gn * Bsz + m0) = out;
    }
}
#define HID_SMEM_BYTES (2 * 3 * (32 * 128 + 32 * 8) * 4)   // 104 KB

// ---------------------------------------------------------------------------
// wab GEMM, split-K over 2 warpgroups (512 threads):
//   C(128, 8450) = At^T(128,512) @ W(512,8450) + bias
// Each warpgroup: R4's proven inner loop (TM=8/TN=4, BK=32, BN=64, S=3
// pipeline) over its half of K, private smem + named barrier. Grid = 133.
// ---------------------------------------------------------------------------
__global__ void __launch_bounds__(512, 1) wab_gemm(const float* __restrict__ At,
                                                   const float* __restrict__ W,
                                                   const float* __restrict__ bias,
                                                   float* __restrict__ C) {
    constexpr int BK = 32, BN = 64, S = 3, NTH = 8, N = OUTSZ;
    constexpr int ASZ = BK * 128, BSZ = BK * BN;       // 4096, 2048
    constexpr int HSZ = S * (ASZ + BSZ);               // 18432 floats per half
    extern __shared__ float sm[];

    const int tid  = threadIdx.x;
    const int wg   = tid >> 8;
    const int wtid = tid & 255;
    float* As = sm + wg * HSZ;
    float* Bs = As + S * ASZ;

    const int n0   = blockIdx.x * BN;
    const int tcol = wtid & 15;         // n-offset tcol*4
    const int trow = wtid >> 4;         // m-offset trow*8

    auto load_tile = [&](int t, int s) {
        int gt = wg * NTH + t;
        float* Ad = As + s * ASZ;
        const float* Ag = At + gt * BK * 128;
#pragma unroll
        for (int u = 0; u < 4; u++) {
            int idx = wtid + u * 256;               // 1024 16B chunks
            int row = idx >> 5, col = (idx & 31) << 2;
            uint32_t d = (uint32_t)__cvta_generic_to_shared(Ad + row * 128 + col);
            asm volatile("cp.async.cg.shared.global [%0], [%1], 16;"
                         :: "r"(d), "l"(Ag + row * 128 + col));
        }
        float* Bd = Bs + s * BSZ;                   // 1024 8B chunks
#pragma unroll
        for (int u = 0; u < 4; u++) {
            int idx = wtid + u * 256;
            int row = idx >> 5, c = (idx & 31) << 1;
            int gn = n0 + c;
            uint32_t d = (uint32_t)__cvta_generic_to_shared(Bd + row * BN + c);
            const float* src = W + (size_t)(gt * BK + row) * N + (gn < N ? gn : 0);
            int bytes = (gn < N) ? 8 : 0;
            asm volatile("cp.async.ca.shared.global [%0], [%1], 8, %2;"
                         :: "r"(d), "l"(src), "r"(bytes));
        }
        asm volatile("cp.async.commit_group;");
    };

    ULL acc[4][4];
#pragma unroll
    for (int i = 0; i < 4; i++)
#pragma unroll
        for (int j = 0; j < 4; j++) acc[i][j] = 0ull;

    load_tile(0, 0);
    load_tile(1, 1);

    for (int t = 0; t < NTH; t++) {
        if (t + 1 < NTH) asm volatile("cp.async.wait_group 1;");
        else             asm volatile("cp.async.wait_group 0;");
        asm volatile("bar.sync %0, 256;" :: "r"(wg + 1));
        if (t + 2 < NTH) load_tile(t + 2, (t + 2) % S);

        const float* As_ = As + (t % S) * ASZ;
        const float* Bs_ = Bs + (t % S) * BSZ;
#pragma unroll
        for (int kk = 0; kk < BK; kk++) {
            const ULL* ap = reinterpret_cast<const ULL*>(As_ + kk * 128 + trow * 8);
            ULL a0 = ap[0], a1 = ap[1], a2 = ap[2], a3 = ap[3];
            float4 bv = *reinterpret_cast<const float4*>(Bs_ + kk * BN + tcol * 4);
            ULL b0 = dup2(bv.x), b1 = dup2(bv.y), b2 = dup2(bv.z), b3 = dup2(bv.w);
            ffma2(acc[0][0], a0, b0); ffma2(acc[0][1], a0, b1);
            ffma2(acc[0][2], a0, b2); ffma2(acc[0][3], a0, b3);
            ffma2(acc[1][0], a1, b0); ffma2(acc[1][1], a1, b1);
            ffma2(acc[1][2], a1, b2); ffma2(acc[1][3], a1, b3);
            ffma2(acc[2][0], a2, b0); ffma2(acc[2][1], a2, b1);
            ffma2(acc[2][2], a2, b2); ffma2(acc[2][3], a2, b3);
            ffma2(acc[3][0], a3, b0); ffma2(acc[3][1], a3, b1);
            ffma2(acc[3][2], a3, b2); ffma2(acc[3][3], a3, b3);
        }
        asm volatile("bar.sync %0, 256;" :: "r"(wg + 1));
    }

    // Cross-warpgroup reduction: wg1 stores 16 pair-accs, wg0 adds + epilogue.
    __syncthreads();
    ULL* red = reinterpret_cast<ULL*>(sm);      // 256*16 ULL = 32 KB, fits
    if (wg == 1) {
#pragma unroll
        for (int i = 0; i < 4; i++)
#pragma unroll
            for (int j = 0; j < 4; j++) red[wtid * 16 + i * 4 + j] = acc[i][j];
    }
    __syncthreads();
    if (wg == 0) {
#pragma unroll
        for (int i = 0; i < 4; i++)
#pragma unroll
            for (int j = 0; j < 4; j++) fadd2(acc[i][j], red[wtid * 16 + i * 4 + j]);
#pragma unroll
        for (int j = 0; j < 4; j++) {
            int gn = n0 + tcol * 4 + j;
            if (gn < N) {
                float bb = bias[gn];
#pragma unroll
                for (int i = 0; i < 4; i++) {
                    float lo, hi;
                    unpack2(acc[i][j], lo, hi);
                    int m = trow * 8 + 2 * i;
                    C[(size_t)m * N + gn]       = lo + bb;
                    C[(size_t)(m + 1) * N + gn] = hi + bb;
                }
            }
        }
    }
}
#define WAB_SMEM_BYTES (2 * 3 * (32 * 128 + 32 * 64) * 4)   // 144 KB

// ---------------------------------------------------------------------------
// Decoder (R4 known-good): one block per b, one thread per g.
// ---------------------------------------------------------------------------
#define SW1 0        // 4096
#define SW2 4096     // 4096
#define SW0 8192     // 64
#define SW3 8256     // 64
#define SB1 8320     // 64
#define SB2 8384     // 64
#define SB0 8448
#define SB3 8449
#define SX  8452
#define XSTRIDE 65
#define DEC_SMEM_FLOATS (SX + 128 * XSTRIDE)
#define DEC_SMEM_BYTES  (DEC_SMEM_FLOATS * 4)

__device__ __forceinline__ void dec_layer(const float* __restrict__ s,
                                          float* __restrict__ xs,
                                          int wbase, int bbase) {
    ULL acc[32];
#pragma unroll
    for (int q = 0; q < 16; q++) {
        float4 bb = *reinterpret_cast<const float4*>(s + bbase + q * 4);
        acc[2 * q]     = pack2(bb.x, bb.y);
        acc[2 * q + 1] = pack2(bb.z, bb.w);
    }
#pragma unroll 4
    for (int i = 0; i < Dd; i++) {
        ULL vd = dup2(xs[i]);
        const ULL* wr = reinterpret_cast<const ULL*>(s + wbase + i * Dd);
#pragma unroll
        for (int q = 0; q < 32; q++) ffma2(acc[q], vd, wr[q]);
    }
#pragma unroll
    for (int q = 0; q < 32; q++) {
        float lo, hi;
        unpack2(acc[q], lo, hi);
        xs[2 * q]     = __sinf(lo);
        xs[2 * q + 1] = __sinf(hi);
    }
}

__global__ void __launch_bounds__(128) decoder_kernel(const float* __restrict__ log_P,
                                                      float* __restrict__ out) {
    extern __shared__ float s[];
    const int b = blockIdx.x;
    const int tid = threadIdx.x;
    const float* gw = g_wab + (size_t)b * OUTSZ;

    for (int i = tid; i < 4096; i += 128) s[SW1 + i] = gw[65 + i];
    for (int i = tid; i < 4096; i += 128) s[SW2 + i] = gw[4225 + i];
    if (tid < 64) {
        s[SW0 + tid] = gw[tid];
        s[SW3 + tid] = gw[8385 + tid];
        s[SB1 + tid] = gw[4161 + tid];
        s[SB2 + tid] = gw[8321 + tid];
    }
    if (tid == 0) { s[SB0] = gw[64]; s[SB3] = gw[8449]; }
    __syncthreads();

    if (tid < Gsz) {
        float x = log_P[b * Gsz + tid] * (1.f / 3.f);
        float* xs = &s[SX + tid * XSTRIDE];
        float b0 = s[SB0];
#pragma unroll
        for (int j = 0; j < Dd; j++)
            xs[j] = __sinf(30.f * fmaf(x, s[SW0 + j], b0));

        dec_layer(s, xs, SW1, SB1);
        dec_layer(s, xs, SW2, SB2);

        float accf = s[SB3];
#pragma unroll
        for (int i = 0; i < Dd; i++) accf = fmaf(xs[i], s[SW3 + i], accf);
        out[b * Gsz + tid] = fmaf(accf, 500.f, 1500.f);
    }
}

// ---------------------------------------------------------------------------
// Launch
// ---------------------------------------------------------------------------
extern "C" void kernel_launch(void* const* d_in, const int* in_sizes, int n_in,
                              void* d_out, int out_size) {
    const float* z     = (const float*)d_in[0];
    const float* log_P = (const float*)d_in[1];
    const float* hW0   = (const float*)d_in[2];
    const float* hb0   = (const float*)d_in[3];
    const float* hW1   = (const float*)d_in[4];
    const float* hb1   = (const float*)d_in[5];
    const float* hW2   = (const float*)d_in[6];
    const float* hb2   = (const float*)d_in[7];
    const float* hWo   = (const float*)d_in[8];
    const float* hbo   = (const float*)d_in[9];
    float* out = (float*)d_out;

    float *h0tp, *h1tp, *h2tp, *wabp;
    cudaGetSymbolAddress((void**)&h0tp, g_h0t);
    cudaGetSymbolAddress((void**)&h1tp, g_h1t);
    cudaGetSymbolAddress((void**)&h2tp, g_h2t);
    cudaGetSymbolAddress((void**)&wabp, g_wab);

    cudaFuncSetAttribute(hid_gemm, cudaFuncAttributeMaxDynamicSharedMemorySize,
                         HID_SMEM_BYTES);
    cudaFuncSetAttribute(wab_gemm, cudaFuncAttributeMaxDynamicSharedMemorySize,
                         WAB_SMEM_BYTES);
    cudaFuncSetAttribute(decoder_kernel, cudaFuncAttributeMaxDynamicSharedMemorySize,
                         DEC_SMEM_BYTES);

    k_h0<<<Bsz, HL>>>(z, hW0, hb0);
    hid_gemm<<<HL / 8, 512, HID_SMEM_BYTES>>>(h0tp, hW1, hb1, h1tp);
    hid_gemm<<<HL / 8, 512, HID_SMEM_BYTES>>>(h1tp, hW2, hb2, h2tp);
    wab_gemm<<<(OUTSZ + 63) / 64, 512, WAB_SMEM_BYTES>>>(h2tp, hWo, hbo, wabp);
    decoder_kernel<<<Bsz, 128, DEC_SMEM_BYTES>>>(log_P, out);
}

// round 9
// speedup vs baseline: 1.1388x; 1.0547x over previous
#include <cuda_runtime.h>
#include <cuda_bf16.h>
#include <cstdint>

// Problem constants
#define Bsz   128
#define Gsz   100
#define Lz    16
#define HL    512
#define Dd    64
#define OUTSZ 8450   // 64+1 + 4096+64 + 4096+64 + 64+1

typedef unsigned long long ULL;

// Scratch (device globals). Hidden activations transposed [k][m].
__device__ __align__(16) float g_h0t[HL * Bsz];
__device__ __align__(16) float g_h1t[HL * Bsz];
__device__ __align__(16) float g_h2t[HL * Bsz];
__device__ __align__(16) float g_wab[Bsz * OUTSZ];

__device__ __forceinline__ float leaky(float v) { return v > 0.f ? v : 0.01f * v; }

// ---- packed fp32x2 helpers ----
__device__ __forceinline__ ULL pack2(float lo, float hi) {
    ULL r; asm("mov.b64 %0, {%1, %2};" : "=l"(r) : "f"(lo), "f"(hi)); return r;
}
__device__ __forceinline__ ULL dup2(float x) {
    ULL r; asm("mov.b64 %0, {%1, %1};" : "=l"(r) : "f"(x)); return r;
}
__device__ __forceinline__ void unpack2(ULL v, float& lo, float& hi) {
    asm("mov.b64 {%0, %1}, %2;" : "=f"(lo), "=f"(hi) : "l"(v));
}
__device__ __forceinline__ void ffma2(ULL& acc, ULL a, ULL b) {
    asm("fma.rn.f32x2 %0, %1, %2, %0;" : "+l"(acc) : "l"(a), "l"(b));
}

// ---- warp MMA primitives (sm_80 baseline PTX: legal at target sm_100) ----
__device__ __forceinline__ uint32_t smem_u32(const void* p) {
    uint32_t a;
    asm("{ .reg .u64 t; cvta.to.shared.u64 t, %1; cvt.u32.u64 %0, t; }"
        : "=r"(a) : "l"(p));
    return a;
}
__device__ __forceinline__ void ldmA(uint32_t* a, uint32_t addr) {
    asm volatile("ldmatrix.sync.aligned.m8n8.x4.trans.shared.b16 {%0,%1,%2,%3}, [%4];"
                 : "=r"(a[0]), "=r"(a[1]), "=r"(a[2]), "=r"(a[3]) : "r"(addr));
}
__device__ __forceinline__ void ldmB(uint32_t& b0, uint32_t& b1, uint32_t addr) {
    asm volatile("ldmatrix.sync.aligned.m8n8.x2.trans.shared.b16 {%0,%1}, [%2];"
                 : "=r"(b0), "=r"(b1) : "r"(addr));
}
__device__ __forceinline__ void mma16816(float* c, const uint32_t* a,
                                         uint32_t b0, uint32_t b1) {
    asm volatile("mma.sync.aligned.m16n8k16.row.col.f32.bf16.bf16.f32 "
                 "{%0,%1,%2,%3}, {%4,%5,%6,%7}, {%8,%9}, {%0,%1,%2,%3};"
                 : "+f"(c[0]), "+f"(c[1]), "+f"(c[2]), "+f"(c[3])
                 : "r"(a[0]), "r"(a[1]), "r"(a[2]), "r"(a[3]), "r"(b0), "r"(b1));
}

__device__ __forceinline__ void split3b(float x, uint16_t& h, uint16_t& m, uint16_t& l) {
    __nv_bfloat16 bh = __float2bfloat16(x);
    float r = x - __bfloat162float(bh);
    __nv_bfloat16 bm = __float2bfloat16(r);
    float r2 = r - __bfloat162float(bm);
    __nv_bfloat16 bl = __float2bfloat16(r2);
    h = *reinterpret_cast<uint16_t*>(&bh);
    m = *reinterpret_cast<uint16_t*>(&bm);
    l = *reinterpret_cast<uint16_t*>(&bl);
}

// ---------------------------------------------------------------------------
// Kernel 1: h0t[j][b] = leaky(z[b] . hW0[:,j] + hb0[j])
// ---------------------------------------------------------------------------
__global__ void k_h0(const float* __restrict__ z, const float* __restrict__ hW0,
                     const float* __restrict__ hb0) {
    __shared__ float zs[Lz];
    int b = blockIdx.x;
    int j = threadIdx.x;
    if (j < Lz) zs[j] = z[b * Lz + j];
    __syncthreads();
    float acc = hb0[j];
#pragma unroll
    for (int i = 0; i < Lz; i++) acc = fmaf(zs[i], hW0[i * HL + j], acc);
    g_h0t[j * Bsz + b] = leaky(acc);
}

// ---------------------------------------------------------------------------
// Hidden GEMM (pipelined, trans-A, trans-out), BN=4 -> grid 128:
//   Ct[n][m] = leaky( sum_k At[k][m] * W[k][n] + bias[n] )
// ---------------------------------------------------------------------------
__global__ void __launch_bounds__(256, 1) hid_gemm(const float* __restrict__ At,
                                                   const float* __restrict__ W,
                                                   const float* __restrict__ bias,
                                                   float* __restrict__ Ct) {
    constexpr int BK = 64, BN = 4, S = 3, K = 512, NT = K / BK;
    constexpr int ASZ = BK * 128;
    constexpr int BSZ = BK * BN;
    extern __shared__ float sm[];
    float* As = sm;
    float* Bs = sm + S * ASZ;

    const int tid  = threadIdx.x;
    const int n0   = blockIdx.x * BN;
    const int tcol = tid & 3;
    const int trow = tid >> 2;       // 0..63
    const int m0   = trow * 2;

    auto load_tile = [&](int t, int s) {
        float* Ad = As + s * ASZ;
        const float* Ag = At + t * BK * 128;
#pragma unroll
        for (int u = 0; u < 8; u++) {
            int idx = tid + u * 256;
            int row = idx >> 5, col = (idx & 31) << 2;
            uint32_t d = (uint32_t)__cvta_generic_to_shared(Ad + row * 128 + col);
            asm volatile("cp.async.cg.shared.global [%0], [%1], 16;"
                         :: "r"(d), "l"(Ag + row * 128 + col));
        }
        if (tid < 64) {
            float* Bd = Bs + s * BSZ;
            uint32_t d = (uint32_t)__cvta_generic_to_shared(Bd + tid * BN);
            asm volatile("cp.async.ca.shared.global [%0], [%1], 16;"
                         :: "r"(d), "l"(W + (size_t)(t * BK + tid) * HL + n0));
        }
        asm volatile("cp.async.commit_group;");
    };

    ULL acc = 0;
    load_tile(0, 0);
    load_tile(1, 1);

    for (int t = 0; t < NT; t++) {
        if (t + 1 < NT) asm volatile("cp.async.wait_group 1;");
        else            asm volatile("cp.async.wait_group 0;");
        __syncthreads();
        if (t + 2 < NT) load_tile(t + 2, (t + 2) % S);

        const float* As_ = As + (t % S) * ASZ;
        const float* Bs_ = Bs + (t % S) * BSZ;
#pragma unroll
        for (int kk = 0; kk < BK; kk++) {
            ULL a = *reinterpret_cast<const ULL*>(As_ + kk * 128 + m0);
            ULL bd = dup2(Bs_[kk * BN + tcol]);
            ffma2(acc, a, bd);
        }
        __syncthreads();
    }

    float v0, v1;
    unpack2(acc, v0, v1);
    int gn = n0 + tcol;
    float bb = bias[gn];
    float2 out = make_float2(leaky(v0 + bb), leaky(v1 + bb));
    *reinterpret_cast<float2*>(Ct + gn * Bsz + m0) = out;
}
#define HID_SMEM_BYTES (3 * (64 * 128 + 64 * 4) * 4)   // ~99 KB

// ---------------------------------------------------------------------------
// wab GEMM on mma.sync bf16 (6-pass 3-term split -> ~fp32 precision):
//   C(128, 8450) = At^T(128,512) @ W(512,8450) + bias
// Grid 133 (BN=64), 256 threads = 8 warps (warp w -> rows 16w..16w+15).
// Per 64-k chunk: split fp32 -> 3 bf16 tiles in smem, ldmatrix.trans + mma.
// A tiles: [k][m] 64x128 bf16, row stride 136 (272 B). B: [k][n] 64x64,
// stride 72 (144 B). All ldmatrix row addrs 16B-aligned, bank-conflict-free.
// ---------------------------------------------------------------------------
#define WA_STR  136
#define WB_STR  72
#define WA_TILE (64 * WA_STR * 2)          // 17408 B
#define WB_TILE (64 * WB_STR * 2)          // 9216 B
#define WA_OFF(p) ((p) * WA_TILE)
#define WB_OFF(p) (3 * WA_TILE + (p) * WB_TILE)
#define WMS_SMEM  (3 * WA_TILE + 3 * WB_TILE)   // 79872 B

__global__ void __launch_bounds__(256, 1) wab_mma(const float* __restrict__ At,
                                                  const float* __restrict__ W,
                                                  const float* __restrict__ bias,
                                                  float* __restrict__ C) {
    constexpr int N = OUTSZ, NCH = 8;
    extern __shared__ char smc[];
    const int tid  = threadIdx.x;
    const int wid  = tid >> 5;
    const int lane = tid & 31;
    const int n0   = blockIdx.x * 64;
    const int m0   = wid * 16;
    const uint32_t sb = smem_u32(smc);

    float acc[8][4];
#pragma unroll
    for (int i = 0; i < 8; i++)
#pragma unroll
        for (int j = 0; j < 4; j++) acc[i][j] = 0.f;

    // per-lane ldmatrix offsets (bytes, within a tile)
    const int g  = lane >> 3, l = lane & 7;
    const uint32_t a_lane = (uint32_t)((((g >> 1) & 1) * 8 + l) * (WA_STR * 2)
                                       + (m0 + (g & 1) * 8) * 2);
    const int lb = lane & 15;
    const uint32_t b_lane = (uint32_t)((((lb >> 3) * 8) + (lb & 7)) * (WB_STR * 2));

    for (int c = 0; c < NCH; c++) {
        const int k0 = c * 64;

        // ---- split A: At[k0+k][m] fp32 -> 3 bf16 tiles [k][m] ----
#pragma unroll
        for (int u = 0; u < 8; u++) {
            int slot = tid + u * 256;              // 2048 float4 slots
            int k = slot >> 5, m4 = (slot & 31) << 2;
            float4 v = *reinterpret_cast<const float4*>(At + (size_t)(k0 + k) * 128 + m4);
            float vv[4] = {v.x, v.y, v.z, v.w};
            uint16_t h[4], m[4], lo[4];
#pragma unroll
            for (int e = 0; e < 4; e++) split3b(vv[e], h[e], m[e], lo[e]);
            uint32_t base = (uint32_t)(k * (WA_STR * 2) + m4 * 2);
            *reinterpret_cast<uint2*>(smc + WA_OFF(0) + base) =
                make_uint2((uint32_t)h[0] | ((uint32_t)h[1] << 16),
                           (uint32_t)h[2] | ((uint32_t)h[3] << 16));
            *reinterpret_cast<uint2*>(smc + WA_OFF(1) + base) =
                make_uint2((uint32_t)m[0] | ((uint32_t)m[1] << 16),
                           (uint32_t)m[2] | ((uint32_t)m[3] << 16));
            *reinterpret_cast<uint2*>(smc + WA_OFF(2) + base) =
                make_uint2((uint32_t)lo[0] | ((uint32_t)lo[1] << 16),
                           (uint32_t)lo[2] | ((uint32_t)lo[3] << 16));
        }
        // ---- split B: W[k0+k][n0+n] fp32 -> 3 bf16 tiles [k][n] ----
#pragma unroll
        for (int u = 0; u < 8; u++) {
            int slot = tid + u * 256;              // 2048 float2 slots
            int k = slot >> 5, n2 = (slot & 31) << 1;
            int g0 = n0 + n2;
            float w0 = 0.f, w1 = 0.f;
            if (g0 + 1 < N) {
                float2 wv = *reinterpret_cast<const float2*>(W + (size_t)(k0 + k) * N + g0);
                w0 = wv.x; w1 = wv.y;
            } else if (g0 < N) {
                w0 = W[(size_t)(k0 + k) * N + g0];
            }
            uint16_t h0, m0_, l0, h1, m1_, l1;
            split3b(w0, h0, m0_, l0);
            split3b(w1, h1, m1_, l1);
            uint32_t base = (uint32_t)(k * (WB_STR * 2) + n2 * 2);
            *reinterpret_cast<uint32_t*>(smc + WB_OFF(0) + base) =
                (uint32_t)h0 | ((uint32_t)h1 << 16);
            *reinterpret_cast<uint32_t*>(smc + WB_OFF(1) + base) =
                (uint32_t)m0_ | ((uint32_t)m1_ << 16);
            *reinterpret_cast<uint32_t*>(smc + WB_OFF(2) + base) =
                (uint32_t)l0 | ((uint32_t)l1 << 16);
        }
        __syncthreads();

        // ---- MMA: 4 k16-steps x 8 n-tiles x 6 split passes ----
#pragma unroll
        for (int ks = 0; ks < 4; ks++) {
            uint32_t ao = a_lane + (uint32_t)(ks * 16 * WA_STR * 2);
            uint32_t Ah[4], Am[4], Al[4];
            ldmA(Ah, sb + WA_OFF(0) + ao);
            ldmA(Am, sb + WA_OFF(1) + ao);
            ldmA(Al, sb + WA_OFF(2) + ao);
            uint32_t bo = b_lane + (uint32_t)(ks * 16 * WB_STR * 2);
#pragma unroll
            for (int nt = 0; nt < 8; nt++) {
                uint32_t off = bo + (uint32_t)(nt * 16);
                uint32_t bh0, bh1, bm0, bm1, bl0, bl1;
                ldmB(bh0, bh1, sb + WB_OFF(0) + off);
                ldmB(bm0, bm1, sb + WB_OFF(1) + off);
                ldmB(bl0, bl1, sb + WB_OFF(2) + off);
                mma16816(acc[nt], Ah, bh0, bh1);   // hi*hi
                mma16816(acc[nt], Ah, bm0, bm1);   // hi*mid
                mma16816(acc[nt], Am, bh0, bh1);   // mid*hi
                mma16816(acc[nt], Am, bm0, bm1);   // mid*mid
                mma16816(acc[nt], Ah, bl0, bl1);   // hi*lo
                mma16816(acc[nt], Al, bh0, bh1);   // lo*hi
            }
        }
        __syncthreads();
    }

    // ---- Epilogue: fragment layout -> C + bias ----
    const int r0 = m0 + (lane >> 2);
    const int r1 = r0 + 8;
    const int cb0 = (lane & 3) * 2;
#pragma unroll
    for (int nt = 0; nt < 8; nt++) {
        int gc = n0 + nt * 8 + cb0;
        if (gc + 1 < N) {
            float b0v = bias[gc], b1v = bias[gc + 1];
            *reinterpret_cast<float2*>(C + (size_t)r0 * N + gc) =
                make_float2(acc[nt][0] + b0v, acc[nt][1] + b1v);
            *reinterpret_cast<float2*>(C + (size_t)r1 * N + gc) =
                make_float2(acc[nt][2] + b0v, acc[nt][3] + b1v);
        } else if (gc < N) {
            float b0v = bias[gc];
            C[(size_t)r0 * N + gc] = acc[nt][0] + b0v;
            C[(size_t)r1 * N + gc] = acc[nt][2] + b0v;
        }
    }
}

// ---------------------------------------------------------------------------
// Decoder (R4 known-good): one block per b, one thread per g.
// ---------------------------------------------------------------------------
#define SW1 0        // 4096
#define SW2 4096     // 4096
#define SW0 8192     // 64
#define SW3 8256     // 64
#define SB1 8320     // 64
#define SB2 8384     // 64
#define SB0 8448
#define SB3 8449
#define SX  8452
#define XSTRIDE 65
#define DEC_SMEM_FLOATS (SX + 128 * XSTRIDE)
#define DEC_SMEM_BYTES  (DEC_SMEM_FLOATS * 4)

__device__ __forceinline__ void dec_layer(const float* __restrict__ s,
                                          float* __restrict__ xs,
                                          int wbase, int bbase) {
    ULL acc[32];
#pragma unroll
    for (int q = 0; q < 16; q++) {
        float4 bb = *reinterpret_cast<const float4*>(s + bbase + q * 4);
        acc[2 * q]     = pack2(bb.x, bb.y);
        acc[2 * q + 1] = pack2(bb.z, bb.w);
    }
#pragma unroll 4
    for (int i = 0; i < Dd; i++) {
        ULL vd = dup2(xs[i]);
        const ULL* wr = reinterpret_cast<const ULL*>(s + wbase + i * Dd);
#pragma unroll
        for (int q = 0; q < 32; q++) ffma2(acc[q], vd, wr[q]);
    }
#pragma unroll
    for (int q = 0; q < 32; q++) {
        float lo, hi;
        unpack2(acc[q], lo, hi);
        xs[2 * q]     = __sinf(lo);
        xs[2 * q + 1] = __sinf(hi);
    }
}

__global__ void __launch_bounds__(128) decoder_kernel(const float* __restrict__ log_P,
                                                      float* __restrict__ out) {
    extern __shared__ float s[];
    const int b = blockIdx.x;
    const int tid = threadIdx.x;
    const float* gw = g_wab + (size_t)b * OUTSZ;

    for (int i = tid; i < 4096; i += 128) s[SW1 + i] = gw[65 + i];
    for (int i = tid; i < 4096; i += 128) s[SW2 + i] = gw[4225 + i];
    if (tid < 64) {
        s[SW0 + tid] = gw[tid];
        s[SW3 + tid] = gw[8385 + tid];
        s[SB1 + tid] = gw[4161 + tid];
        s[SB2 + tid] = gw[8321 + tid];
    }
    if (tid == 0) { s[SB0] = gw[64]; s[SB3] = gw[8449]; }
    __syncthreads();

    if (tid < Gsz) {
        float x = log_P[b * Gsz + tid] * (1.f / 3.f);
        float* xs = &s[SX + tid * XSTRIDE];
        float b0 = s[SB0];
#pragma unroll
        for (int j = 0; j < Dd; j++)
            xs[j] = __sinf(30.f * fmaf(x, s[SW0 + j], b0));

        dec_layer(s, xs, SW1, SB1);
        dec_layer(s, xs, SW2, SB2);

        float accf = s[SB3];
#pragma unroll
        for (int i = 0; i < Dd; i++) accf = fmaf(xs[i], s[SW3 + i], accf);
        out[b * Gsz + tid] = fmaf(accf, 500.f, 1500.f);
    }
}

// ---------------------------------------------------------------------------
// Launch
// ---------------------------------------------------------------------------
extern "C" void kernel_launch(void* const* d_in, const int* in_sizes, int n_in,
                              void* d_out, int out_size) {
    const float* z     = (const float*)d_in[0];
    const float* log_P = (const float*)d_in[1];
    const float* hW0   = (const float*)d_in[2];
    const float* hb0   = (const float*)d_in[3];
    const float* hW1   = (const float*)d_in[4];
    const float* hb1   = (const float*)d_in[5];
    const float* hW2   = (const float*)d_in[6];
    const float* hb2   = (const float*)d_in[7];
    const float* hWo   = (const float*)d_in[8];
    const float* hbo   = (const float*)d_in[9];
    float* out = (float*)d_out;

    float *h0tp, *h1tp, *h2tp, *wabp;
    cudaGetSymbolAddress((void**)&h0tp, g_h0t);
    cudaGetSymbolAddress((void**)&h1tp, g_h1t);
    cudaGetSymbolAddress((void**)&h2tp, g_h2t);
    cudaGetSymbolAddress((void**)&wabp, g_wab);

    cudaFuncSetAttribute(hid_gemm, cudaFuncAttributeMaxDynamicSharedMemorySize,
                         HID_SMEM_BYTES);
    cudaFuncSetAttribute(wab_mma, cudaFuncAttributeMaxDynamicSharedMemorySize,
                         WMS_SMEM);
    cudaFuncSetAttribute(decoder_kernel, cudaFuncAttributeMaxDynamicSharedMemorySize,
                         DEC_SMEM_BYTES);

    k_h0<<<Bsz, HL>>>(z, hW0, hb0);
    hid_gemm<<<HL / 4, 256, HID_SMEM_BYTES>>>(h0tp, hW1, hb1, h1tp);
    hid_gemm<<<HL / 4, 256, HID_SMEM_BYTES>>>(h1tp, hW2, hb2, h2tp);
    wab_mma<<<(OUTSZ + 63) / 64, 256, WMS_SMEM>>>(h2tp, hWo, hbo, wabp);
    decoder_kernel<<<Bsz, 128, DEC_SMEM_BYTES>>>(log_P, out);
}